// round 2
// baseline (speedup 1.0000x reference)
#include <cuda_runtime.h>
#include <cuda_bf16.h>
#include <cstdint>

// Problem constants (fixed by the dataset)
#define NNODES 50000
#define LEV 2
#define RR 2
#define BLK (RR*LEV)          // 4 framelet blocks
#define NNZ 800000
#define F_IN 128
#define F_OUT 64
#define ACT_B (BLK - (LEV-1)) // 3 active blocks (block 0's y is never used)

// Scratch (device globals — no runtime allocation allowed).
// Declared as float4 so 16B alignment of every vector access is guaranteed.
__device__ float4 g_h[(size_t)NNODES * (F_OUT/4)];            // 12.8 MB
__device__ float4 g_y[(size_t)ACT_B * NNODES * (F_OUT/4)];    // 38.4 MB

// ---------------------------------------------------------------------------
// Kernel 1: h = x @ W   (x: [N,128], W: [128,64] row-major, h: [N,64])
// 256 threads/block, 16 rows/block. W + x tile staged in smem.
// ---------------------------------------------------------------------------
__global__ __launch_bounds__(256) void gemm_xw(const float* __restrict__ x,
                                               const float* __restrict__ w) {
    __shared__ float4 ws[F_IN * (F_OUT/4)];   // 32 KB, W row-major as float4
    __shared__ float4 xs[16 * (F_IN/4)];      // 8 KB
    const int t = threadIdx.x;

    // Load W (8192 floats = 2048 float4, 8 per thread)
    #pragma unroll
    for (int i = 0; i < 8; i++)
        ws[t + i * 256] = ((const float4*)w)[t + i * 256];

    // Load 16-row x tile (2048 floats = 512 float4, 2 per thread)
    const size_t row0 = (size_t)blockIdx.x * 16;
    #pragma unroll
    for (int i = 0; i < 2; i++)
        xs[t + i * 256] = ((const float4*)x)[row0 * (F_IN/4) + t + i * 256];

    __syncthreads();

    const int fi = t & 15;    // which float4 of the 16 output-float4s
    const int ri = t >> 4;    // row within tile
    float4 acc = make_float4(0.f, 0.f, 0.f, 0.f);

    #pragma unroll
    for (int k = 0; k < F_IN; k += 4) {
        const float4 xv = xs[ri * (F_IN/4) + (k >> 2)];
        const float4 w0 = ws[(k + 0) * 16 + fi];
        const float4 w1 = ws[(k + 1) * 16 + fi];
        const float4 w2 = ws[(k + 2) * 16 + fi];
        const float4 w3 = ws[(k + 3) * 16 + fi];
        acc.x += xv.x * w0.x + xv.y * w1.x + xv.z * w2.x + xv.w * w3.x;
        acc.y += xv.x * w0.y + xv.y * w1.y + xv.z * w2.y + xv.w * w3.y;
        acc.z += xv.x * w0.z + xv.y * w1.z + xv.z * w2.z + xv.w * w3.z;
        acc.w += xv.x * w0.w + xv.y * w1.w + xv.z * w2.w + xv.w * w3.w;
    }
    g_h[(row0 + ri) * (F_OUT/4) + fi] = acc;
}

// ---------------------------------------------------------------------------
// Kernel 2: zero y scratch + init out with bias
// ---------------------------------------------------------------------------
__global__ __launch_bounds__(256) void init_bufs(float* __restrict__ out,
                                                 const float* __restrict__ bias) {
    const size_t YF4 = (size_t)ACT_B * NNODES * (F_OUT/4);   // 2.4M float4
    const size_t OF4 = (size_t)NNODES * (F_OUT/4);           // 800K float4
    size_t i = (size_t)blockIdx.x * blockDim.x + threadIdx.x;
    const size_t stride = (size_t)gridDim.x * blockDim.x;
    const float4 z = make_float4(0.f, 0.f, 0.f, 0.f);
    for (size_t j = i; j < YF4; j += stride)
        g_y[j] = z;
    for (size_t j = i; j < OF4; j += stride) {
        const int fi = (int)(j & 15);
        ((float4*)out)[j] = ((const float4*)bias)[fi];
    }
}

__device__ __forceinline__ void red_add_v4(float4* p, float4 v) {
    asm volatile("red.global.add.v4.f32 [%0], {%1,%2,%3,%4};"
                 :: "l"(p), "f"(v.x), "f"(v.y), "f"(v.z), "f"(v.w) : "memory");
}

// ---------------------------------------------------------------------------
// Kernel 3: SpMM-1 with folded filter:  y[b] += filt[b,r] * v * h[c]
// Active blocks b = 1..3 (stored at g_y slots 0..2). 16 threads per edge.
// ---------------------------------------------------------------------------
__global__ __launch_bounds__(256) void spmm1(const float* __restrict__ vals,
                                             const int*   __restrict__ rows,
                                             const int*   __restrict__ cols,
                                             const float* __restrict__ filt) {
    const size_t gt = (size_t)blockIdx.x * blockDim.x + threadIdx.x;
    const size_t TOT = (size_t)ACT_B * NNZ * 16;
    if (gt >= TOT) return;
    const int    q = (int)(gt & 15);
    const size_t e = gt >> 4;                  // 0 .. 2.4M-1
    const int    b = (int)(e / NNZ);           // 0..2  (active slot)
    const size_t i = e - (size_t)b * NNZ;
    const size_t src = (size_t)(b + 1) * NNZ + i;   // real block index b+1

    const int r = rows[src];
    const int c = cols[src];
    const float v = vals[src] * filt[(size_t)(b + 1) * NNODES + r];

    const float4 hv = g_h[(size_t)c * 16 + q];
    float4* dst = g_y + ((size_t)b * NNODES + r) * 16 + q;
    red_add_v4(dst, make_float4(v * hv.x, v * hv.y, v * hv.z, v * hv.w));
}

// ---------------------------------------------------------------------------
// Kernel 4: SpMM-2:  out += v * y[b][c]   summed over active blocks
// ---------------------------------------------------------------------------
__global__ __launch_bounds__(256) void spmm2(const float* __restrict__ vals,
                                             const int*   __restrict__ rows,
                                             const int*   __restrict__ cols,
                                             float* __restrict__ out) {
    const size_t gt = (size_t)blockIdx.x * blockDim.x + threadIdx.x;
    const size_t TOT = (size_t)ACT_B * NNZ * 16;
    if (gt >= TOT) return;
    const int    q = (int)(gt & 15);
    const size_t e = gt >> 4;
    const int    b = (int)(e / NNZ);
    const size_t i = e - (size_t)b * NNZ;
    const size_t src = (size_t)(b + 1) * NNZ + i;

    const int r = rows[src];
    const int c = cols[src];
    const float v = vals[src];

    const float4 yv = g_y[((size_t)b * NNODES + c) * 16 + q];
    float4* dst = ((float4*)out) + (size_t)r * 16 + q;
    red_add_v4(dst, make_float4(v * yv.x, v * yv.y, v * yv.z, v * yv.w));
}

// ---------------------------------------------------------------------------
// Launch: gemm -> init -> spmm1 -> spmm2   (single stream preserves order)
// ---------------------------------------------------------------------------
extern "C" void kernel_launch(void* const* d_in, const int* in_sizes, int n_in,
                              void* d_out, int out_size) {
    const float* x    = (const float*)d_in[0];
    const float* wgt  = (const float*)d_in[1];
    const float* filt = (const float*)d_in[2];
    const float* bias = (const float*)d_in[3];
    const float* vals = (const float*)d_in[4];
    const int*   rows = (const int*)d_in[5];
    const int*   cols = (const int*)d_in[6];
    float* out = (float*)d_out;

    // h = x @ W : 3125 blocks of 16 rows
    gemm_xw<<<NNODES / 16, 256>>>(x, wgt);
    // zero y + bias-init out
    init_bufs<<<2048, 256>>>(out, bias);

    const size_t TOT = (size_t)ACT_B * NNZ * 16;     // 38.4M threads
    const int blocks = (int)((TOT + 255) / 256);     // 150000
    spmm1<<<blocks, 256>>>(vals, rows, cols, filt);
    spmm2<<<blocks, 256>>>(vals, rows, cols, out);
}

// round 3
// speedup vs baseline: 1.6529x; 1.6529x over previous
#include <cuda_runtime.h>
#include <cuda_bf16.h>
#include <cstdint>

// Problem constants (fixed by the dataset)
#define NNODES 50000
#define LEV 2
#define RR 2
#define BLK (RR*LEV)          // 4 framelet blocks
#define NNZ 800000
#define F_IN 128
#define F_OUT 64
#define ACT_B (BLK - (LEV-1)) // 3 active blocks (block 0's y is never used)
#define ROWS_T (ACT_B * NNODES)   // 150000 (b, r) rows
#define EDGES_T (ACT_B * NNZ)     // 2400000 active edges
#define NB1 ((ROWS_T + 255) / 256)  // 586 level-1 scan blocks

// ---------------------------------------------------------------------------
// Device-global scratch (no runtime allocation allowed)
// ---------------------------------------------------------------------------
__device__ float4 g_h[(size_t)NNODES * (F_OUT/4)];     // 12.8 MB  h = xW
__device__ float4 g_y[(size_t)ROWS_T * (F_OUT/4)];     // 38.4 MB  y (blocks 1..3)
__device__ int    g_hist[ROWS_T];                      // per-(b,r) nnz
__device__ int    g_start[ROWS_T];                     // CSR row starts (exclusive scan)
__device__ int    g_cursor[ROWS_T];                    // scatter cursors
__device__ int    g_part[1024];                        // scan block partials
__device__ int2   g_ev[EDGES_T];                       // packed (col, val) sorted by row

// ---------------------------------------------------------------------------
// Kernel 1: h = x @ W   (x: [N,128], W: [128,64] row-major, h: [N,64])
// ---------------------------------------------------------------------------
__global__ __launch_bounds__(256) void gemm_xw(const float* __restrict__ x,
                                               const float* __restrict__ w) {
    __shared__ float4 ws[F_IN * (F_OUT/4)];   // 32 KB
    __shared__ float4 xs[16 * (F_IN/4)];      // 8 KB
    const int t = threadIdx.x;

    #pragma unroll
    for (int i = 0; i < 8; i++)
        ws[t + i * 256] = ((const float4*)w)[t + i * 256];

    const size_t row0 = (size_t)blockIdx.x * 16;
    #pragma unroll
    for (int i = 0; i < 2; i++)
        xs[t + i * 256] = ((const float4*)x)[row0 * (F_IN/4) + t + i * 256];

    __syncthreads();

    const int fi = t & 15;
    const int ri = t >> 4;
    float4 acc = make_float4(0.f, 0.f, 0.f, 0.f);

    #pragma unroll
    for (int k = 0; k < F_IN; k += 4) {
        const float4 xv = xs[ri * (F_IN/4) + (k >> 2)];
        const float4 w0 = ws[(k + 0) * 16 + fi];
        const float4 w1 = ws[(k + 1) * 16 + fi];
        const float4 w2 = ws[(k + 2) * 16 + fi];
        const float4 w3 = ws[(k + 3) * 16 + fi];
        acc.x += xv.x * w0.x + xv.y * w1.x + xv.z * w2.x + xv.w * w3.x;
        acc.y += xv.x * w0.y + xv.y * w1.y + xv.z * w2.y + xv.w * w3.y;
        acc.z += xv.x * w0.z + xv.y * w1.z + xv.z * w2.z + xv.w * w3.z;
        acc.w += xv.x * w0.w + xv.y * w1.w + xv.z * w2.w + xv.w * w3.w;
    }
    g_h[(row0 + ri) * (F_OUT/4) + fi] = acc;
}

// ---------------------------------------------------------------------------
// Sort stage: counting sort of active edges by destination row r
// ---------------------------------------------------------------------------
__global__ __launch_bounds__(256) void hist_zero() {
    const int i = blockIdx.x * 256 + threadIdx.x;
    if (i < ROWS_T) g_hist[i] = 0;
    if (i < 1024)   g_part[i] = 0;
}

__global__ __launch_bounds__(256) void hist_build(const int* __restrict__ rows) {
    const int e = blockIdx.x * 256 + threadIdx.x;
    if (e >= EDGES_T) return;
    const int b = e / NNZ;
    const int i = e - b * NNZ;
    const int r = rows[(size_t)(b + 1) * NNZ + i];
    atomicAdd(&g_hist[b * NNODES + r], 1);
}

// Level-1 scan: per-256 block exclusive prescan, block totals into g_part
__global__ __launch_bounds__(256) void scan1() {
    __shared__ int s[256];
    const int t = threadIdx.x;
    const int idx = blockIdx.x * 256 + t;
    const int v = (idx < ROWS_T) ? g_hist[idx] : 0;
    s[t] = v;
    __syncthreads();
    #pragma unroll
    for (int off = 1; off < 256; off <<= 1) {
        const int a = (t >= off) ? s[t - off] : 0;
        __syncthreads();
        s[t] += a;
        __syncthreads();
    }
    if (idx < ROWS_T) g_start[idx] = s[t] - v;   // exclusive within block
    if (t == 255)     g_part[blockIdx.x] = s[t]; // block total
}

// Level-2 scan: single block scans the (<=1024) block totals, exclusive
__global__ __launch_bounds__(1024) void scan2() {
    __shared__ int s[1024];
    const int t = threadIdx.x;
    const int v = g_part[t];
    s[t] = v;
    __syncthreads();
    #pragma unroll
    for (int off = 1; off < 1024; off <<= 1) {
        const int a = (t >= off) ? s[t - off] : 0;
        __syncthreads();
        s[t] += a;
        __syncthreads();
    }
    g_part[t] = s[t] - v;
}

// Level-3: add block offsets; also seed the scatter cursors
__global__ __launch_bounds__(256) void scan3() {
    const int idx = blockIdx.x * 256 + threadIdx.x;
    if (idx >= ROWS_T) return;
    const int v = g_start[idx] + g_part[blockIdx.x];
    g_start[idx] = v;
    g_cursor[idx] = v;
}

// Scatter edges into row-sorted packed (col, val) pairs
__global__ __launch_bounds__(256) void scatter(const float* __restrict__ vals,
                                               const int*   __restrict__ rows,
                                               const int*   __restrict__ cols) {
    const int e = blockIdx.x * 256 + threadIdx.x;
    if (e >= EDGES_T) return;
    const int b = e / NNZ;
    const int i = e - b * NNZ;
    const size_t src = (size_t)(b + 1) * NNZ + i;
    const int r = rows[src];
    const int c = cols[src];
    const float v = vals[src];
    const int pos = atomicAdd(&g_cursor[b * NNODES + r], 1);
    g_ev[pos] = make_int2(c, __float_as_int(v));
}

// ---------------------------------------------------------------------------
// SpMM-1 (CSR, gather-only): y[b][r] = filt[b][r] * sum_e v_e * h[c_e]
// 16 lanes per row; each lane owns one float4 column chunk.
// ---------------------------------------------------------------------------
__global__ __launch_bounds__(256) void spmm1_csr(const float* __restrict__ filt) {
    const int gid = blockIdx.x * 256 + threadIdx.x;
    const int row = gid >> 4;                 // (b, r) flat: 0..149999
    const int q   = gid & 15;
    const int beg = g_start[row];
    const int len = g_hist[row];
    const int b = row / NNODES;
    const int r = row - b * NNODES;

    float4 acc = make_float4(0.f, 0.f, 0.f, 0.f);
    #pragma unroll 2
    for (int j = beg; j < beg + len; j++) {
        const int2 ev = g_ev[j];              // broadcast within the 16-lane group
        const float v = __int_as_float(ev.y);
        const float4 hv = g_h[(size_t)ev.x * 16 + q];
        acc.x += v * hv.x; acc.y += v * hv.y;
        acc.z += v * hv.z; acc.w += v * hv.w;
    }
    const float f = filt[(size_t)(b + 1) * NNODES + r];
    g_y[(size_t)row * 16 + q] = make_float4(f * acc.x, f * acc.y, f * acc.z, f * acc.w);
}

// ---------------------------------------------------------------------------
// SpMM-2 (CSR, gather-only): out[r] = bias + sum_b sum_e v_e * y[b][c_e]
// ---------------------------------------------------------------------------
__global__ __launch_bounds__(256) void spmm2_csr(float* __restrict__ out,
                                                 const float* __restrict__ bias) {
    const int gid = blockIdx.x * 256 + threadIdx.x;
    const int r = gid >> 4;                   // 0..49999
    const int q = gid & 15;

    float4 acc = ((const float4*)bias)[q];
    #pragma unroll
    for (int b = 0; b < ACT_B; b++) {
        const int row = b * NNODES + r;
        const int beg = g_start[row];
        const int len = g_hist[row];
        const size_t ybase = (size_t)b * NNODES * 16;
        #pragma unroll 2
        for (int j = beg; j < beg + len; j++) {
            const int2 ev = g_ev[j];
            const float v = __int_as_float(ev.y);
            const float4 yv = g_y[ybase + (size_t)ev.x * 16 + q];
            acc.x += v * yv.x; acc.y += v * yv.y;
            acc.z += v * yv.z; acc.w += v * yv.w;
        }
    }
    ((float4*)out)[(size_t)r * 16 + q] = acc;
}

// ---------------------------------------------------------------------------
// Launch sequence (single stream): gemm, sort pipeline, spmm1, spmm2
// ---------------------------------------------------------------------------
extern "C" void kernel_launch(void* const* d_in, const int* in_sizes, int n_in,
                              void* d_out, int out_size) {
    const float* x    = (const float*)d_in[0];
    const float* wgt  = (const float*)d_in[1];
    const float* filt = (const float*)d_in[2];
    const float* bias = (const float*)d_in[3];
    const float* vals = (const float*)d_in[4];
    const int*   rows = (const int*)d_in[5];
    const int*   cols = (const int*)d_in[6];
    float* out = (float*)d_out;

    gemm_xw<<<NNODES / 16, 256>>>(x, wgt);

    hist_zero<<<NB1, 256>>>();
    hist_build<<<(EDGES_T + 255) / 256, 256>>>(rows);
    scan1<<<NB1, 256>>>();
    scan2<<<1, 1024>>>();
    scan3<<<NB1, 256>>>();
    scatter<<<(EDGES_T + 255) / 256, 256>>>(vals, rows, cols);

    spmm1_csr<<<(ROWS_T * 16) / 256, 256>>>(filt);          // 9375 blocks
    spmm2_csr<<<(NNODES * 16) / 256, 256>>>(out, bias);     // 3125 blocks
}

// round 6
// speedup vs baseline: 1.8557x; 1.1227x over previous
#include <cuda_runtime.h>
#include <cuda_fp16.h>
#include <cstdint>

// Problem constants (fixed by the dataset)
#define NNODES 50000
#define LEV 2
#define RR 2
#define BLK (RR*LEV)          // 4 framelet blocks
#define NNZ 800000
#define F_IN 128
#define F_OUT 64
#define ACT_B (BLK - (LEV-1)) // 3 active blocks (block 0's y is never used)
#define ROWS_T (ACT_B * NNODES)   // 150000 (b, r) rows
#define EDGES_T (ACT_B * NNZ)     // 2400000 active edges
#define NB1 ((ROWS_T + 255) / 256)  // 586 level-1 scan blocks

// ---------------------------------------------------------------------------
// Device-global scratch. h and y stored fp16 (half2-packed): row = 64 halves
// = 128 B = 8 uint4.
// ---------------------------------------------------------------------------
__device__ uint4 g_h[(size_t)NNODES * 8];     // 6.4 MB
__device__ uint4 g_y[(size_t)ROWS_T * 8];     // 19.2 MB
__device__ int   g_hist[ROWS_T];              // per-(b,r) nnz
__device__ int   g_start[ROWS_T];             // block-local exclusive prefix
__device__ int   g_cursor[ROWS_T];            // scatter cursors (block-local)
__device__ int   g_part[1024];                // scan block partials (exclusive)
__device__ int2  g_ev[EDGES_T];               // (col, val-bits) sorted by row

__device__ __forceinline__ unsigned pack_h2(float a, float b) {
    __half2 h = __floats2half2_rn(a, b);
    return *reinterpret_cast<unsigned*>(&h);
}
__device__ __forceinline__ float2 unpack_h2(unsigned u) {
    __half2 h = *reinterpret_cast<__half2*>(&u);
    return __half22float2(h);
}

// ---------------------------------------------------------------------------
// Kernel 1: h = x @ W  (fp32 compute, fp16 store)  + zero g_hist (fused)
// ---------------------------------------------------------------------------
__global__ __launch_bounds__(256) void gemm_xw(const float* __restrict__ x,
                                               const float* __restrict__ w) {
    const int t = threadIdx.x;
    const int gt = blockIdx.x * 256 + t;     // 3125*256 = 800000 >= ROWS_T
    if (gt < ROWS_T) g_hist[gt] = 0;

    __shared__ float4 ws[F_IN * (F_OUT/4)];   // 32 KB
    __shared__ float4 xs[16 * (F_IN/4)];      // 8 KB

    #pragma unroll
    for (int i = 0; i < 8; i++)
        ws[t + i * 256] = ((const float4*)w)[t + i * 256];

    const size_t row0 = (size_t)blockIdx.x * 16;
    #pragma unroll
    for (int i = 0; i < 2; i++)
        xs[t + i * 256] = ((const float4*)x)[row0 * (F_IN/4) + t + i * 256];

    __syncthreads();

    const int fi = t & 15;
    const int ri = t >> 4;
    float4 acc = make_float4(0.f, 0.f, 0.f, 0.f);

    #pragma unroll
    for (int k = 0; k < F_IN; k += 4) {
        const float4 xv = xs[ri * (F_IN/4) + (k >> 2)];
        const float4 w0 = ws[(k + 0) * 16 + fi];
        const float4 w1 = ws[(k + 1) * 16 + fi];
        const float4 w2 = ws[(k + 2) * 16 + fi];
        const float4 w3 = ws[(k + 3) * 16 + fi];
        acc.x += xv.x * w0.x + xv.y * w1.x + xv.z * w2.x + xv.w * w3.x;
        acc.y += xv.x * w0.y + xv.y * w1.y + xv.z * w2.y + xv.w * w3.y;
        acc.z += xv.x * w0.z + xv.y * w1.z + xv.z * w2.z + xv.w * w3.z;
        acc.w += xv.x * w0.w + xv.y * w1.w + xv.z * w2.w + xv.w * w3.w;
    }
    uint2 p;
    p.x = pack_h2(acc.x, acc.y);
    p.y = pack_h2(acc.z, acc.w);
    ((uint2*)g_h)[(row0 + ri) * 16 + fi] = p;
}

// ---------------------------------------------------------------------------
// Sort stage (counting sort of active edges by destination row).
// hist_build / scatter: 2 edges per thread, vectorized index loads.
// Active edges are rows[NNZ .. 4*NNZ) — contiguous, NNZ even.
// ---------------------------------------------------------------------------
__global__ __launch_bounds__(256) void hist_build(const int* __restrict__ rows) {
    const int p = blockIdx.x * 256 + threadIdx.x;      // pair index
    if (p >= EDGES_T / 2) return;
    const int2 rp = ((const int2*)(rows + NNZ))[p];    // edges 2p, 2p+1
    const int e0 = 2 * p;
    const int b0 = e0 / NNZ;                           // both edges same block
    atomicAdd(&g_hist[b0 * NNODES + rp.x], 1);
    atomicAdd(&g_hist[b0 * NNODES + rp.y], 1);
}

// Level-1 scan: block-local exclusive prefix; totals to g_part; seeds cursors
__global__ __launch_bounds__(256) void scan1() {
    __shared__ int s[256];
    const int t = threadIdx.x;
    const int idx = blockIdx.x * 256 + t;
    const int v = (idx < ROWS_T) ? g_hist[idx] : 0;
    s[t] = v;
    __syncthreads();
    #pragma unroll
    for (int off = 1; off < 256; off <<= 1) {
        const int a = (t >= off) ? s[t - off] : 0;
        __syncthreads();
        s[t] += a;
        __syncthreads();
    }
    if (idx < ROWS_T) {
        const int ex = s[t] - v;
        g_start[idx]  = ex;
        g_cursor[idx] = ex;
    }
    if (t == 255) g_part[blockIdx.x] = s[t];
}

// Level-2: single block exclusive-scans the block totals (guarded: stale
// g_part entries persist across graph replays).
__global__ __launch_bounds__(1024) void scan2() {
    __shared__ int s[1024];
    const int t = threadIdx.x;
    const int v = (t < NB1) ? g_part[t] : 0;
    s[t] = v;
    __syncthreads();
    #pragma unroll
    for (int off = 1; off < 1024; off <<= 1) {
        const int a = (t >= off) ? s[t - off] : 0;
        __syncthreads();
        s[t] += a;
        __syncthreads();
    }
    if (t < NB1) g_part[t] = s[t] - v;
}

// Scatter: 2 edges per thread; global pos = local cursor + scanned block part
__global__ __launch_bounds__(256) void scatter(const float* __restrict__ vals,
                                               const int*   __restrict__ rows,
                                               const int*   __restrict__ cols) {
    const int p = blockIdx.x * 256 + threadIdx.x;
    if (p >= EDGES_T / 2) return;
    const int2   rp = ((const int2*)(rows + NNZ))[p];
    const int2   cp = ((const int2*)(cols + NNZ))[p];
    const float2 vp = ((const float2*)(vals + NNZ))[p];
    const int b0 = (2 * p) / NNZ;
    const int base = b0 * NNODES;

    const int bk0 = base + rp.x;
    const int pos0 = atomicAdd(&g_cursor[bk0], 1) + g_part[bk0 >> 8];
    g_ev[pos0] = make_int2(cp.x, __float_as_int(vp.x));

    const int bk1 = base + rp.y;
    const int pos1 = atomicAdd(&g_cursor[bk1], 1) + g_part[bk1 >> 8];
    g_ev[pos1] = make_int2(cp.y, __float_as_int(vp.y));
}

// ---------------------------------------------------------------------------
// SpMM-1 (CSR gather): y[b][r] = filt[b][r] * sum_e v_e * h[c_e]
// 8 lanes per row; each lane owns 8 halves (one uint4, 16 B).
// ---------------------------------------------------------------------------
__global__ __launch_bounds__(256) void spmm1_csr(const float* __restrict__ filt) {
    const int gid = blockIdx.x * 256 + threadIdx.x;
    const int row = gid >> 3;
    if (row >= ROWS_T) return;
    const int q = gid & 7;
    const int beg = g_start[row] + g_part[row >> 8];
    const int len = g_hist[row];
    const int b = row / NNODES;
    const int r = row - b * NNODES;

    float acc[8];
    #pragma unroll
    for (int k = 0; k < 8; k++) acc[k] = 0.f;

    const int2* ev = g_ev + beg;
    #pragma unroll 2
    for (int j = 0; j < len; j++) {
        const int2 e = ev[j];
        const float v = __int_as_float(e.y);
        const uint4 hv = g_h[(size_t)e.x * 8 + q];
        const float2 f0 = unpack_h2(hv.x);
        const float2 f1 = unpack_h2(hv.y);
        const float2 f2 = unpack_h2(hv.z);
        const float2 f3 = unpack_h2(hv.w);
        acc[0] += v * f0.x; acc[1] += v * f0.y;
        acc[2] += v * f1.x; acc[3] += v * f1.y;
        acc[4] += v * f2.x; acc[5] += v * f2.y;
        acc[6] += v * f3.x; acc[7] += v * f3.y;
    }
    const float f = filt[(size_t)(b + 1) * NNODES + r];
    uint4 o;
    o.x = pack_h2(f * acc[0], f * acc[1]);
    o.y = pack_h2(f * acc[2], f * acc[3]);
    o.z = pack_h2(f * acc[4], f * acc[5]);
    o.w = pack_h2(f * acc[6], f * acc[7]);
    g_y[(size_t)row * 8 + q] = o;
}

// ---------------------------------------------------------------------------
// SpMM-2 (CSR gather): out[r] = bias + sum_b sum_e v_e * y[b][c_e]
// ---------------------------------------------------------------------------
__global__ __launch_bounds__(256) void spmm2_csr(float* __restrict__ out,
                                                 const float* __restrict__ bias) {
    const int gid = blockIdx.x * 256 + threadIdx.x;
    const int r = gid >> 3;
    if (r >= NNODES) return;
    const int q = gid & 7;

    float acc[8];
    #pragma unroll
    for (int k = 0; k < 8; k++) acc[k] = bias[q * 8 + k];

    #pragma unroll
    for (int b = 0; b < ACT_B; b++) {
        const int row = b * NNODES + r;
        const int beg = g_start[row] + g_part[row >> 8];
        const int len = g_hist[row];
        const size_t ybase = (size_t)b * NNODES * 8;
        const int2* ev = g_ev + beg;
        #pragma unroll 2
        for (int j = 0; j < len; j++) {
            const int2 e = ev[j];
            const float v = __int_as_float(e.y);
            const uint4 yv = g_y[ybase + (size_t)e.x * 8 + q];
            const float2 f0 = unpack_h2(yv.x);
            const float2 f1 = unpack_h2(yv.y);
            const float2 f2 = unpack_h2(yv.z);
            const float2 f3 = unpack_h2(yv.w);
            acc[0] += v * f0.x; acc[1] += v * f0.y;
            acc[2] += v * f1.x; acc[3] += v * f1.y;
            acc[4] += v * f2.x; acc[5] += v * f2.y;
            acc[6] += v * f3.x; acc[7] += v * f3.y;
        }
    }
    float4* op = (float4*)(out + (size_t)r * F_OUT + q * 8);
    op[0] = make_float4(acc[0], acc[1], acc[2], acc[3]);
    op[1] = make_float4(acc[4], acc[5], acc[6], acc[7]);
}

// ---------------------------------------------------------------------------
// Launch: gemm(+zero), hist, scan1, scan2, scatter, spmm1 (#6 -> ncu), spmm2
// ---------------------------------------------------------------------------
extern "C" void kernel_launch(void* const* d_in, const int* in_sizes, int n_in,
                              void* d_out, int out_size) {
    const float* x    = (const float*)d_in[0];
    const float* wgt  = (const float*)d_in[1];
    const float* filt = (const float*)d_in[2];
    const float* bias = (const float*)d_in[3];
    const float* vals = (const float*)d_in[4];
    const int*   rows = (const int*)d_in[5];
    const int*   cols = (const int*)d_in[6];
    float* out = (float*)d_out;

    gemm_xw<<<NNODES / 16, 256>>>(x, wgt);                         // #1
    hist_build<<<(EDGES_T / 2 + 255) / 256, 256>>>(rows);          // #2
    scan1<<<NB1, 256>>>();                                         // #3
    scan2<<<1, 1024>>>();                                          // #4
    scatter<<<(EDGES_T / 2 + 255) / 256, 256>>>(vals, rows, cols); // #5
    spmm1_csr<<<(ROWS_T * 8 + 255) / 256, 256>>>(filt);            // #6
    spmm2_csr<<<(NNODES * 8 + 255) / 256, 256>>>(out, bias);       // #7
}